// round 11
// baseline (speedup 1.0000x reference)
#include <cuda_runtime.h>
#include <cuda_bf16.h>
#include <cstdint>

#define BB 256
#define TT 256
#define CP1 129
#define HH 128
#define G1 384
#define PRED_N (BB * (TT - 1) * 128)
#define PAR_N  (BB * TT * 2)

typedef unsigned long long ull;
typedef unsigned int u32;

// ---------------- scratch: __device__ globals -------------------------------
__device__ float g_gi1[(size_t)BB * TT * G1];   // (b,t,384) layer-1 input proj
__device__ float g_out1[(size_t)BB * TT * HH];  // (b,t,128) layer-1 outputs

// ---------------- helpers ----------------------------------------------------
__device__ __forceinline__ ull fma2(ull a, ull b, ull c) {
    ull d; asm("fma.rn.f32x2 %0,%1,%2,%3;" : "=l"(d) : "l"(a), "l"(b), "l"(c));
    return d;
}
__device__ __forceinline__ float2 unpack2(ull v) {
    float lo, hi; asm("mov.b64 {%0,%1},%2;" : "=f"(lo), "=f"(hi) : "l"(v));
    return make_float2(lo, hi);
}
__device__ __forceinline__ float sigf(float v) {
    return __fdividef(1.f, 1.f + __expf(-v));
}
__device__ __forceinline__ float tanh_(float v) {
    return __fdividef(2.f, 1.f + __expf(-2.f * v)) - 1.f;
}
__device__ __forceinline__ u32 smem_u32(const void* p) {
    u32 a;
    asm("{ .reg .u64 t; cvta.to.shared.u64 t, %1; cvt.u32.u64 %0, t; }"
        : "=r"(a) : "l"(p));
    return a;
}
__device__ __forceinline__ void cp_async16(u32 saddr, const void* gaddr) {
    asm volatile("cp.async.cg.shared.global [%0], [%1], 16;"
                 :: "r"(saddr), "l"(gaddr));
}
__device__ __forceinline__ void cp_commit() {
    asm volatile("cp.async.commit_group;");
}
__device__ __forceinline__ void cp_wait1() {
    asm volatile("cp.async.wait_group 1;" ::: "memory");
}
__device__ __forceinline__ void cp_wait0() {
    asm volatile("cp.async.wait_group 0;" ::: "memory");
}

// ---------------- K1: gi1 = x @ Wih1^T + bih1 (unchanged from R8 best) ------
__global__ void __launch_bounds__(256, 3) k_gi1(
        const float* __restrict__ x, const int* __restrict__ lengths,
        const float* __restrict__ Wih1, const float* __restrict__ bih1) {
    int t0 = blockIdx.x * 64, b = blockIdx.y, n0 = blockIdx.z * 64;
    if (t0 >= lengths[b]) return;

    __shared__ __align__(16) float sA[64][36];
    __shared__ __align__(16) float sW[64][36];
    ull acc[4][4];
#pragma unroll
    for (int i = 0; i < 4; i++)
#pragma unroll
        for (int j = 0; j < 4; j++) acc[i][j] = 0ull;

    const float* xb = x + (size_t)(b * TT + t0) * CP1;
    int tx = threadIdx.x & 15, ty = threadIdx.x >> 4;

    for (int kc = 0; kc < 128; kc += 32) {
        __syncthreads();
#pragma unroll
        for (int l = 0; l < 8; l++) {
            int idx = threadIdx.x + l * 256;
            int r = idx >> 5, c = idx & 31;
            sA[r][c] = xb[r * CP1 + kc + c];
            sW[r][c] = Wih1[(size_t)(n0 + r) * CP1 + kc + c];
        }
        __syncthreads();
#pragma unroll
        for (int kq = 0; kq < 8; kq++) {
            ull w[4][2], a[4][2];
#pragma unroll
            for (int j = 0; j < 4; j++) {
                float4 v = *(const float4*)&sW[tx + 16 * j][kq * 4];
                w[j][0] = ((ull*)&v)[0]; w[j][1] = ((ull*)&v)[1];
            }
#pragma unroll
            for (int i = 0; i < 4; i++) {
                float4 v = *(const float4*)&sA[ty + 16 * i][kq * 4];
                a[i][0] = ((ull*)&v)[0]; a[i][1] = ((ull*)&v)[1];
            }
#pragma unroll
            for (int i = 0; i < 4; i++)
#pragma unroll
                for (int j = 0; j < 4; j++) {
                    acc[i][j] = fma2(a[i][0], w[j][0], acc[i][j]);
                    acc[i][j] = fma2(a[i][1], w[j][1], acc[i][j]);
                }
        }
    }
    float at[4], wt[4], bias[4];
#pragma unroll
    for (int i = 0; i < 4; i++) at[i] = xb[(ty + 16 * i) * CP1 + 128];
#pragma unroll
    for (int j = 0; j < 4; j++) {
        wt[j]   = Wih1[(size_t)(n0 + tx + 16 * j) * CP1 + 128];
        bias[j] = bih1[n0 + tx + 16 * j];
    }
#pragma unroll
    for (int i = 0; i < 4; i++) {
        int t = t0 + ty + 16 * i;
        float* orow = g_gi1 + (size_t)(b * TT + t) * G1 + n0;
#pragma unroll
        for (int j = 0; j < 4; j++) {
            float2 p = unpack2(acc[i][j]);
            orow[tx + 16 * j] = p.x + p.y + at[i] * wt[j] + bias[j];
        }
    }
}

// ---------------- K2: fused recurrence, cp.async gi1 ring (depth 2) ---------
// 128 CTAs; CTA p runs batch rows p and 255-p.
__global__ void __launch_bounds__(384, 1)
k_recur1(const int* __restrict__ lengths, const float* __restrict__ h0_1,
         const float* __restrict__ Whh1, const float* __restrict__ bhh1,
         const float* __restrict__ h0_2, const float* __restrict__ Wih2,
         const float* __restrict__ Whh2, const float* __restrict__ bih2,
         const float* __restrict__ bhh2, float* __restrict__ out) {
    int g = threadIdx.x;
    int wid = g >> 5, lane = g & 31;
    ull W2[64];
    const ull* wr = (const ull*)(Whh1 + (size_t)g * HH);
#pragma unroll
    for (int i = 0; i < 64; i++) W2[i] = wr[i];
    float bh = bhh1[g];

    float4 wv2 = make_float4(0.f, 0.f, 0.f, 0.f);
    float bi2 = 0.f;
    if (wid < 6) { wv2 = ((const float4*)Wih2)[wid * 32 + lane]; bi2 = bih2[wid]; }

    __shared__ __align__(16) float s_h[HH];
    __shared__ float s_gh[G1];
    __shared__ float s_gi2[6];
    __shared__ float s_w2[18];
    __shared__ __align__(16) float s_buf[2][G1];   // cp.async gi1 ring
    if (g < 12) s_w2[g] = Whh2[g];
    else if (g < 18) s_w2[g] = bhh2[g - 12];

    u32 sb0 = smem_u32(&s_buf[0][0]);
    u32 sb1 = smem_u32(&s_buf[1][0]);

#pragma unroll 1
    for (int rsel = 0; rsel < 2; rsel++) {
        int b = rsel ? (255 - (int)blockIdx.x) : (int)blockIdx.x;
        int len = lengths[b];
        if (g < HH) s_h[g] = h0_1[b * HH + g];
        float u0 = 0.f, u1 = 0.f;
        if (g == 383) { u0 = h0_2[b * 2]; u1 = h0_2[b * 2 + 1]; }

        const float* gi = g_gi1 + (size_t)b * TT * G1;
        float* o1 = g_out1 + (size_t)b * TT * HH;
        float* par = out + PRED_N + (size_t)b * TT * 2;

        // prologue: step 0 gates direct; step 1 staged via cp.async group
        float pr = 0.f, pz = 0.f, pn = 0.f;
        if (g < HH) { pr = gi[g]; pz = gi[HH + g]; pn = gi[2 * HH + g]; }
        if (g < 96 && 1 < len) cp_async16(sb1 + g * 16, gi + G1 + g * 4);
        cp_commit();
        __syncthreads();

#pragma unroll 1
        for (int t = 0; t < len; t++) {
            // stage gi1[t+2] into the ring slot freed last step
            if (g < 96 && t + 2 < len)
                cp_async16((t & 1 ? sb1 : sb0) + g * 16,
                           gi + (size_t)(t + 2) * G1 + g * 4);
            cp_commit();

            // -------- phase A: Whh1 matvec (LDS.128 broadcasts) -------------
            ull c0 = 0ull, c1 = 0ull, c2 = 0ull, c3 = 0ull;
            const float4* h4 = (const float4*)s_h;
#pragma unroll
            for (int i = 0; i < 32; i += 2) {
                float4 v0 = h4[i], v1 = h4[i + 1];
                c0 = fma2(W2[2 * i],     ((ull*)&v0)[0], c0);
                c1 = fma2(W2[2 * i + 1], ((ull*)&v0)[1], c1);
                c2 = fma2(W2[2 * i + 2], ((ull*)&v1)[0], c2);
                c3 = fma2(W2[2 * i + 3], ((ull*)&v1)[1], c3);
            }
            float2 f0 = unpack2(c0), f1 = unpack2(c1);
            float2 f2 = unpack2(c2), f3 = unpack2(c3);
            s_gh[g] = ((f0.x + f0.y) + (f1.x + f1.y)) +
                      ((f2.x + f2.y) + (f3.x + f3.y)) + bh;

            if (wid < 6 && t >= 1) {   // gi2 of out1[t-1] (== current s_h)
                float4 hv = *(const float4*)&s_h[lane * 4];
                float v = hv.x * wv2.x + hv.y * wv2.y + hv.z * wv2.z + hv.w * wv2.w;
                v += __shfl_xor_sync(0xFFFFFFFFu, v, 16);
                v += __shfl_xor_sync(0xFFFFFFFFu, v, 8);
                v += __shfl_xor_sync(0xFFFFFFFFu, v, 4);
                v += __shfl_xor_sync(0xFFFFFFFFu, v, 2);
                v += __shfl_xor_sync(0xFFFFFFFFu, v, 1);
                if (lane == 0) s_gi2[wid] = v + bi2;
            }
            cp_wait1();        // gi1[t+1] landed in s_buf[(t+1)&1]
            __syncthreads();   // publish to all threads

            // -------- phase B: gate update | layer-2 scalar GRU -------------
            if (g < HH) {
                float r = sigf(pr + s_gh[g]);
                float z = sigf(pz + s_gh[HH + g]);
                float n = tanh_(pn + r * s_gh[2 * HH + g]);
                float hn = (1.f - z) * n + z * s_h[g];
                o1[(size_t)t * HH + g] = hn;
                s_h[g] = hn;
                if (t + 1 < len) {   // next step's gates from smem ring
                    const float* nb = s_buf[(t + 1) & 1];
                    pr = nb[g]; pz = nb[HH + g]; pn = nb[2 * HH + g];
                }
            } else if (g == 383 && t >= 1) {
                float hr0 = s_w2[0]  * u0 + s_w2[1]  * u1 + s_w2[12];
                float hr1 = s_w2[2]  * u0 + s_w2[3]  * u1 + s_w2[13];
                float hz0 = s_w2[4]  * u0 + s_w2[5]  * u1 + s_w2[14];
                float hz1 = s_w2[6]  * u0 + s_w2[7]  * u1 + s_w2[15];
                float hn0 = s_w2[8]  * u0 + s_w2[9]  * u1 + s_w2[16];
                float hn1 = s_w2[10] * u0 + s_w2[11] * u1 + s_w2[17];
                float r0 = sigf(s_gi2[0] + hr0), r1 = sigf(s_gi2[1] + hr1);
                float z0 = sigf(s_gi2[2] + hz0), z1 = sigf(s_gi2[3] + hz1);
                float n0 = tanh_(s_gi2[4] + r0 * hn0), n1 = tanh_(s_gi2[5] + r1 * hn1);
                u0 = (1.f - z0) * n0 + z0 * u0;
                u1 = (1.f - z1) * n1 + z1 * u1;
                par[(t - 1) * 2]     = __expf(-u0);
                par[(t - 1) * 2 + 1] = __expf(-u1);
            }
            __syncthreads();
        }
        cp_wait0();   // drain ring before next row reuses s_buf

        // final layer-2 step (uses out1[len-1] == current s_h)
        if (wid < 6) {
            float4 hv = *(const float4*)&s_h[lane * 4];
            float v = hv.x * wv2.x + hv.y * wv2.y + hv.z * wv2.z + hv.w * wv2.w;
            v += __shfl_xor_sync(0xFFFFFFFFu, v, 16);
            v += __shfl_xor_sync(0xFFFFFFFFu, v, 8);
            v += __shfl_xor_sync(0xFFFFFFFFu, v, 4);
            v += __shfl_xor_sync(0xFFFFFFFFu, v, 2);
            v += __shfl_xor_sync(0xFFFFFFFFu, v, 1);
            if (lane == 0) s_gi2[wid] = v + bi2;
        }
        __syncthreads();
        if (g == 383) {
            float hr0 = s_w2[0]  * u0 + s_w2[1]  * u1 + s_w2[12];
            float hr1 = s_w2[2]  * u0 + s_w2[3]  * u1 + s_w2[13];
            float hz0 = s_w2[4]  * u0 + s_w2[5]  * u1 + s_w2[14];
            float hz1 = s_w2[6]  * u0 + s_w2[7]  * u1 + s_w2[15];
            float hn0 = s_w2[8]  * u0 + s_w2[9]  * u1 + s_w2[16];
            float hn1 = s_w2[10] * u0 + s_w2[11] * u1 + s_w2[17];
            float r0 = sigf(s_gi2[0] + hr0), r1 = sigf(s_gi2[1] + hr1);
            float z0 = sigf(s_gi2[2] + hz0), z1 = sigf(s_gi2[3] + hz1);
            float n0 = tanh_(s_gi2[4] + r0 * hn0), n1 = tanh_(s_gi2[5] + r1 * hn1);
            u0 = (1.f - z0) * n0 + z0 * u0;
            u1 = (1.f - z1) * n1 + z1 * u1;
            par[(len - 1) * 2]     = __expf(-u0);
            par[(len - 1) * 2 + 1] = __expf(-u1);
        }
        for (int tp = len + g; tp < TT; tp += 384) {
            par[tp * 2] = 1.f; par[tp * 2 + 1] = 1.f;
        }
        if (g == 0) out[PRED_N + PAR_N + b] = (float)len;
        __syncthreads();
    }
}

// ---------------- K3: FC head (unchanged from R8 best) ----------------------
__global__ void __launch_bounds__(256, 3) k_fc(
        const float* __restrict__ x, const int* __restrict__ lengths,
        const float* __restrict__ Wfc, const float* __restrict__ bfc,
        float* __restrict__ out) {
    int t0 = blockIdx.x * 64, b = blockIdx.y, n0 = blockIdx.z * 64;
    int len = lengths[b];
    float* ob = out + ((size_t)b * (TT - 1)) * 128;
    int rows = min(64, (TT - 1) - t0);

    if (t0 >= len - 1) {
        for (int idx = threadIdx.x; idx < rows * 64; idx += 256) {
            int m = idx >> 6, n = idx & 63;
            ob[(size_t)(t0 + m) * 128 + n0 + n] = 0.f;
        }
        return;
    }

    __shared__ __align__(16) float sA[64][36];
    __shared__ __align__(16) float sW[64][36];
    ull acc[4][4];
#pragma unroll
    for (int i = 0; i < 4; i++)
#pragma unroll
        for (int j = 0; j < 4; j++) acc[i][j] = 0ull;

    const float* ab = g_out1 + (size_t)(b * TT + t0) * HH;
    int tx = threadIdx.x & 15, ty = threadIdx.x >> 4;

    for (int kc = 0; kc < 128; kc += 32) {
        __syncthreads();
#pragma unroll
        for (int l = 0; l < 8; l++) {
            int idx = threadIdx.x + l * 256;
            int r = idx >> 5, c = idx & 31;
            sA[r][c] = ab[r * HH + kc + c];
            sW[r][c] = Wfc[(size_t)(n0 + r) * CP1 + kc + c];
        }
        __syncthreads();
#pragma unroll
        for (int kq = 0; kq < 8; kq++) {
            ull w[4][2], a[4][2];
#pragma unroll
            for (int j = 0; j < 4; j++) {
                float4 v = *(const float4*)&sW[tx + 16 * j][kq * 4];
                w[j][0] = ((ull*)&v)[0]; w[j][1] = ((ull*)&v)[1];
            }
#pragma unroll
            for (int i = 0; i < 4; i++) {
                float4 v = *(const float4*)&sA[ty + 16 * i][kq * 4];
                a[i][0] = ((ull*)&v)[0]; a[i][1] = ((ull*)&v)[1];
            }
#pragma unroll
            for (int i = 0; i < 4; i++)
#pragma unroll
                for (int j = 0; j < 4; j++) {
                    acc[i][j] = fma2(a[i][0], w[j][0], acc[i][j]);
                    acc[i][j] = fma2(a[i][1], w[j][1], acc[i][j]);
                }
        }
    }
    float at[4], wt[4], bias[4];
#pragma unroll
    for (int i = 0; i < 4; i++) {
        int t = t0 + ty + 16 * i;
        at[i] = x[(size_t)(b * TT + t) * CP1];
    }
#pragma unroll
    for (int j = 0; j < 4; j++) {
        wt[j]   = Wfc[(size_t)(n0 + tx + 16 * j) * CP1 + 128];
        bias[j] = bfc[n0 + tx + 16 * j];
    }
#pragma unroll
    for (int i = 0; i < 4; i++) {
        int t = t0 + ty + 16 * i;
        if (t >= TT - 1) continue;
        float* orow = ob + (size_t)t * 128 + n0;
        bool valid = (t < len - 1);
#pragma unroll
        for (int j = 0; j < 4; j++) {
            float2 p = unpack2(acc[i][j]);
            float v = p.x + p.y + at[i] * wt[j] + bias[j];
            orow[tx + 16 * j] = valid ? v : 0.f;
        }
    }
}

// ---------------- launch -----------------------------------------------------
extern "C" void kernel_launch(void* const* d_in, const int* in_sizes, int n_in,
                              void* d_out, int out_size) {
    const float* x      = (const float*)d_in[0];
    const int*   lens   = (const int*)  d_in[1];
    const float* h0_1   = (const float*)d_in[2];
    const float* h0_2   = (const float*)d_in[3];
    const float* Wih1   = (const float*)d_in[4];
    const float* Whh1   = (const float*)d_in[5];
    const float* bih1   = (const float*)d_in[6];
    const float* bhh1   = (const float*)d_in[7];
    const float* Wih2   = (const float*)d_in[8];
    const float* Whh2   = (const float*)d_in[9];
    const float* bih2   = (const float*)d_in[10];
    const float* bhh2   = (const float*)d_in[11];
    const float* Wfc    = (const float*)d_in[12];
    const float* bfc    = (const float*)d_in[13];
    float* out = (float*)d_out;

    k_gi1  <<<dim3(4, BB, 6), 256>>>(x, lens, Wih1, bih1);
    k_recur1<<<128, 384>>>(lens, h0_1, Whh1, bhh1, h0_2, Wih2, Whh2, bih2, bhh2, out);
    k_fc   <<<dim3(4, BB, 2), 256>>>(x, lens, Wfc, bfc, out);
}

// round 12
// speedup vs baseline: 1.1299x; 1.1299x over previous
#include <cuda_runtime.h>
#include <cuda_bf16.h>
#include <cstdint>

#define BB 256
#define TT 256
#define CP1 129
#define HH 128
#define G1 384
#define PRED_N (BB * (TT - 1) * 128)
#define PAR_N  (BB * TT * 2)

typedef unsigned long long ull;
typedef unsigned int u32;

// ---------------- scratch: __device__ globals -------------------------------
__device__ float g_gi1[(size_t)BB * TT * G1];   // (b,t,384) layer-1 input proj
__device__ float g_out1[(size_t)BB * TT * HH];  // (b,t,128) layer-1 outputs

// ---------------- helpers ----------------------------------------------------
__device__ __forceinline__ ull fma2(ull a, ull b, ull c) {
    ull d; asm("fma.rn.f32x2 %0,%1,%2,%3;" : "=l"(d) : "l"(a), "l"(b), "l"(c));
    return d;
}
__device__ __forceinline__ float2 unpack2(ull v) {
    float lo, hi; asm("mov.b64 {%0,%1},%2;" : "=f"(lo), "=f"(hi) : "l"(v));
    return make_float2(lo, hi);
}
__device__ __forceinline__ float sigf(float v) {
    return __fdividef(1.f, 1.f + __expf(-v));
}
__device__ __forceinline__ float tanh_(float v) {
    return __fdividef(2.f, 1.f + __expf(-2.f * v)) - 1.f;
}
__device__ __forceinline__ u32 f2tf32(float v) {
    u32 r; asm("cvt.rna.tf32.f32 %0, %1;" : "=r"(r) : "f"(v));
    return r;
}

#define MMA_TF32(d, a, b)                                              \
    asm volatile("mma.sync.aligned.m16n8k8.row.col.f32.tf32.tf32.f32 " \
        "{%0,%1,%2,%3}, {%4,%5,%6,%7}, {%8,%9}, {%0,%1,%2,%3};"        \
        : "+f"((d)[0]), "+f"((d)[1]), "+f"((d)[2]), "+f"((d)[3])       \
        : "r"((a)[0]), "r"((a)[1]), "r"((a)[2]), "r"((a)[3]),          \
          "r"((b)[0]), "r"((b)[1]))

// ---------------- K1: gi1 = x @ Wih1^T + bih1  (3xTF32 tensor cores) --------
// Tile 128(t) x 64(n); 8 warps in 4(m) x 2(n); each warp 32x32 via 2x4
// m16n8k8 acc tiles. K staged in 16-chunks as tf32 hi/lo (stride-20 pad:
// fragment loads conflict-free). k=128 tail + bias in fp32 epilogue.
__global__ void __launch_bounds__(256) k_gi1(
        const float* __restrict__ x, const int* __restrict__ lengths,
        const float* __restrict__ Wih1, const float* __restrict__ bih1) {
    int t0 = blockIdx.x * 128, b = blockIdx.y, n0 = blockIdx.z * 64;
    if (t0 >= lengths[b]) return;

    __shared__ __align__(16) float sAh[128][20], sAl[128][20];
    __shared__ __align__(16) float sWh[64][20],  sWl[64][20];

    int tid = threadIdx.x;
    int w = tid >> 5, lane = tid & 31;
    int gid = lane >> 2, tig = lane & 3;
    int mb = (w & 3) * 32, nb = (w >> 2) * 32;

    float d[2][4][4] = {};
    const float* xb = x + (size_t)(b * TT + t0) * CP1;

    for (int kc = 0; kc < 128; kc += 16) {
        __syncthreads();
#pragma unroll
        for (int l = 0; l < 8; l++) {            // A: 128x16
            int idx = tid + l * 256;
            int r = idx >> 4, c = idx & 15;
            float v = xb[r * CP1 + kc + c];
            float hf = __uint_as_float(f2tf32(v));
            sAh[r][c] = hf;
            sAl[r][c] = __uint_as_float(f2tf32(v - hf));
        }
#pragma unroll
        for (int l = 0; l < 4; l++) {            // W: 64x16
            int idx = tid + l * 256;
            int r = idx >> 4, c = idx & 15;
            float v = Wih1[(size_t)(n0 + r) * CP1 + kc + c];
            float hf = __uint_as_float(f2tf32(v));
            sWh[r][c] = hf;
            sWl[r][c] = __uint_as_float(f2tf32(v - hf));
        }
        __syncthreads();
#pragma unroll
        for (int k8 = 0; k8 < 2; k8++) {
            int kk = k8 * 8;
            u32 ah[2][4], al[2][4], bh[4][2], bl[4][2];
#pragma unroll
            for (int mt = 0; mt < 2; mt++) {
                int r = mb + mt * 16 + gid;
                ah[mt][0] = __float_as_uint(sAh[r][kk + tig]);
                ah[mt][1] = __float_as_uint(sAh[r + 8][kk + tig]);
                ah[mt][2] = __float_as_uint(sAh[r][kk + tig + 4]);
                ah[mt][3] = __float_as_uint(sAh[r + 8][kk + tig + 4]);
                al[mt][0] = __float_as_uint(sAl[r][kk + tig]);
                al[mt][1] = __float_as_uint(sAl[r + 8][kk + tig]);
                al[mt][2] = __float_as_uint(sAl[r][kk + tig + 4]);
                al[mt][3] = __float_as_uint(sAl[r + 8][kk + tig + 4]);
            }
#pragma unroll
            for (int nt = 0; nt < 4; nt++) {
                int c = nb + nt * 8 + gid;
                bh[nt][0] = __float_as_uint(sWh[c][kk + tig]);
                bh[nt][1] = __float_as_uint(sWh[c][kk + tig + 4]);
                bl[nt][0] = __float_as_uint(sWl[c][kk + tig]);
                bl[nt][1] = __float_as_uint(sWl[c][kk + tig + 4]);
            }
#pragma unroll
            for (int mt = 0; mt < 2; mt++)
#pragma unroll
                for (int nt = 0; nt < 4; nt++) {
                    MMA_TF32(d[mt][nt], al[mt], bh[nt]);
                    MMA_TF32(d[mt][nt], ah[mt], bl[nt]);
                    MMA_TF32(d[mt][nt], ah[mt], bh[nt]);
                }
        }
    }

    // epilogue: k=128 tail + bias + store (fp32)
    float at_[2][2], wt_[4][2], bi_[4][2];
#pragma unroll
    for (int mt = 0; mt < 2; mt++) {
        int r = mb + mt * 16 + gid;
        at_[mt][0] = xb[r * CP1 + 128];
        at_[mt][1] = xb[(r + 8) * CP1 + 128];
    }
#pragma unroll
    for (int nt = 0; nt < 4; nt++) {
        int c0 = n0 + nb + nt * 8 + 2 * tig;
        wt_[nt][0] = Wih1[(size_t)c0 * CP1 + 128];
        wt_[nt][1] = Wih1[(size_t)(c0 + 1) * CP1 + 128];
        bi_[nt][0] = bih1[c0];
        bi_[nt][1] = bih1[c0 + 1];
    }
#pragma unroll
    for (int mt = 0; mt < 2; mt++) {
        int r = mb + mt * 16 + gid;
        float* row0 = g_gi1 + (size_t)(b * TT + t0 + r) * G1 + n0;
        float* row1 = row0 + (size_t)8 * G1;
#pragma unroll
        for (int nt = 0; nt < 4; nt++) {
            int c = nb + nt * 8 + 2 * tig;
            float2 v0 = make_float2(
                d[mt][nt][0] + at_[mt][0] * wt_[nt][0] + bi_[nt][0],
                d[mt][nt][1] + at_[mt][0] * wt_[nt][1] + bi_[nt][1]);
            float2 v1 = make_float2(
                d[mt][nt][2] + at_[mt][1] * wt_[nt][0] + bi_[nt][0],
                d[mt][nt][3] + at_[mt][1] * wt_[nt][1] + bi_[nt][1]);
            *(float2*)(row0 + c) = v0;
            *(float2*)(row1 + c) = v1;
        }
    }
}

// ---------------- K2: fused recurrence (R8 base; gi2 reduce moved first) ----
__global__ void __launch_bounds__(384, 1)
k_recur1(const int* __restrict__ lengths, const float* __restrict__ h0_1,
         const float* __restrict__ Whh1, const float* __restrict__ bhh1,
         const float* __restrict__ h0_2, const float* __restrict__ Wih2,
         const float* __restrict__ Whh2, const float* __restrict__ bih2,
         const float* __restrict__ bhh2, float* __restrict__ out) {
    int g = threadIdx.x;
    int wid = g >> 5, lane = g & 31;
    ull W2[64];
    const ull* wr = (const ull*)(Whh1 + (size_t)g * HH);
#pragma unroll
    for (int i = 0; i < 64; i++) W2[i] = wr[i];
    float bh = bhh1[g];

    float4 wv2 = make_float4(0.f, 0.f, 0.f, 0.f);
    float bi2 = 0.f;
    if (wid < 6) { wv2 = ((const float4*)Wih2)[wid * 32 + lane]; bi2 = bih2[wid]; }

    __shared__ __align__(16) float s_h[HH];
    __shared__ float s_gh[G1];
    __shared__ float s_gi2[6];
    __shared__ float s_w2[18];   // Whh2 (12) + bhh2 (6)
    if (g < 12) s_w2[g] = Whh2[g];
    else if (g < 18) s_w2[g] = bhh2[g - 12];

#pragma unroll 1
    for (int rsel = 0; rsel < 2; rsel++) {
        int b = rsel ? (255 - (int)blockIdx.x) : (int)blockIdx.x;
        int len = lengths[b];
        if (g < HH) s_h[g] = h0_1[b * HH + g];
        float u0 = 0.f, u1 = 0.f;
        if (g == 383) { u0 = h0_2[b * 2]; u1 = h0_2[b * 2 + 1]; }
        __syncthreads();

        const float* gi = g_gi1 + (size_t)b * TT * G1;
        float* o1 = g_out1 + (size_t)b * TT * HH;
        float* par = out + PRED_N + (size_t)b * TT * 2;
        float pr = 0.f, pz = 0.f, pn = 0.f;
        if (g < HH) { pr = gi[g]; pz = gi[HH + g]; pn = gi[2 * HH + g]; }

#pragma unroll 1
        for (int t = 0; t < len; t++) {
            // -------- phase A: gi2 shfl-reduce FIRST (chain hides under
            //          the matvec issue stream), then Whh1 matvec ------------
            if (wid < 6 && t >= 1) {   // gi2 of out1[t-1] (== current s_h)
                float4 hv = *(const float4*)&s_h[lane * 4];
                float v = hv.x * wv2.x + hv.y * wv2.y + hv.z * wv2.z + hv.w * wv2.w;
                v += __shfl_xor_sync(0xFFFFFFFFu, v, 16);
                v += __shfl_xor_sync(0xFFFFFFFFu, v, 8);
                v += __shfl_xor_sync(0xFFFFFFFFu, v, 4);
                v += __shfl_xor_sync(0xFFFFFFFFu, v, 2);
                v += __shfl_xor_sync(0xFFFFFFFFu, v, 1);
                if (lane == 0) s_gi2[wid] = v + bi2;
            }

            ull a0 = 0ull, a1 = 0ull, a2 = 0ull, a3 = 0ull;
            const ull* h2 = (const ull*)s_h;
#pragma unroll
            for (int i = 0; i < 64; i += 4) {
                a0 = fma2(W2[i],     h2[i],     a0);
                a1 = fma2(W2[i + 1], h2[i + 1], a1);
                a2 = fma2(W2[i + 2], h2[i + 2], a2);
                a3 = fma2(W2[i + 3], h2[i + 3], a3);
            }
            float2 f0 = unpack2(a0), f1 = unpack2(a1);
            float2 f2 = unpack2(a2), f3 = unpack2(a3);
            s_gh[g] = ((f0.x + f0.y) + (f1.x + f1.y)) +
                      ((f2.x + f2.y) + (f3.x + f3.y)) + bh;
            __syncthreads();

            // -------- phase B: gate update | layer-2 scalar GRU -------------
            if (g < HH) {
                float r = sigf(pr + s_gh[g]);
                float z = sigf(pz + s_gh[HH + g]);
                float n = tanh_(pn + r * s_gh[2 * HH + g]);
                float hn = (1.f - z) * n + z * s_h[g];
                o1[(size_t)t * HH + g] = hn;
                if (t + 1 < len) {
                    const float* gn = gi + (size_t)(t + 1) * G1;
                    pr = gn[g]; pz = gn[HH + g]; pn = gn[2 * HH + g];
                }
                s_h[g] = hn;
            } else if (g == 383 && t >= 1) {
                float hr0 = s_w2[0]  * u0 + s_w2[1]  * u1 + s_w2[12];
                float hr1 = s_w2[2]  * u0 + s_w2[3]  * u1 + s_w2[13];
                float hz0 = s_w2[4]  * u0 + s_w2[5]  * u1 + s_w2[14];
                float hz1 = s_w2[6]  * u0 + s_w2[7]  * u1 + s_w2[15];
                float hn0 = s_w2[8]  * u0 + s_w2[9]  * u1 + s_w2[16];
                float hn1 = s_w2[10] * u0 + s_w2[11] * u1 + s_w2[17];
                float r0 = sigf(s_gi2[0] + hr0), r1 = sigf(s_gi2[1] + hr1);
                float z0 = sigf(s_gi2[2] + hz0), z1 = sigf(s_gi2[3] + hz1);
                float n0 = tanh_(s_gi2[4] + r0 * hn0), n1 = tanh_(s_gi2[5] + r1 * hn1);
                u0 = (1.f - z0) * n0 + z0 * u0;
                u1 = (1.f - z1) * n1 + z1 * u1;
                par[(t - 1) * 2]     = __expf(-u0);
                par[(t - 1) * 2 + 1] = __expf(-u1);
            }
            __syncthreads();
        }

        // final layer-2 step (uses out1[len-1] == current s_h)
        if (wid < 6) {
            float4 hv = *(const float4*)&s_h[lane * 4];
            float v = hv.x * wv2.x + hv.y * wv2.y + hv.z * wv2.z + hv.w * wv2.w;
            v += __shfl_xor_sync(0xFFFFFFFFu, v, 16);
            v += __shfl_xor_sync(0xFFFFFFFFu, v, 8);
            v += __shfl_xor_sync(0xFFFFFFFFu, v, 4);
            v += __shfl_xor_sync(0xFFFFFFFFu, v, 2);
            v += __shfl_xor_sync(0xFFFFFFFFu, v, 1);
            if (lane == 0) s_gi2[wid] = v + bi2;
        }
        __syncthreads();
        if (g == 383) {
            float hr0 = s_w2[0]  * u0 + s_w2[1]  * u1 + s_w2[12];
            float hr1 = s_w2[2]  * u0 + s_w2[3]  * u1 + s_w2[13];
            float hz0 = s_w2[4]  * u0 + s_w2[5]  * u1 + s_w2[14];
            float hz1 = s_w2[6]  * u0 + s_w2[7]  * u1 + s_w2[15];
            float hn0 = s_w2[8]  * u0 + s_w2[9]  * u1 + s_w2[16];
            float hn1 = s_w2[10] * u0 + s_w2[11] * u1 + s_w2[17];
            float r0 = sigf(s_gi2[0] + hr0), r1 = sigf(s_gi2[1] + hr1);
            float z0 = sigf(s_gi2[2] + hz0), z1 = sigf(s_gi2[3] + hz1);
            float n0 = tanh_(s_gi2[4] + r0 * hn0), n1 = tanh_(s_gi2[5] + r1 * hn1);
            u0 = (1.f - z0) * n0 + z0 * u0;
            u1 = (1.f - z1) * n1 + z1 * u1;
            par[(len - 1) * 2]     = __expf(-u0);
            par[(len - 1) * 2 + 1] = __expf(-u1);
        }
        for (int tp = len + g; tp < TT; tp += 384) {
            par[tp * 2] = 1.f; par[tp * 2 + 1] = 1.f;
        }
        if (g == 0) out[PRED_N + PAR_N + b] = (float)len;
        __syncthreads();
    }
}

// ---------------- K3: FC head (unchanged from R8 best, fp32 f32x2) ----------
__global__ void __launch_bounds__(256, 3) k_fc(
        const float* __restrict__ x, const int* __restrict__ lengths,
        const float* __restrict__ Wfc, const float* __restrict__ bfc,
        float* __restrict__ out) {
    int t0 = blockIdx.x * 64, b = blockIdx.y, n0 = blockIdx.z * 64;
    int len = lengths[b];
    float* ob = out + ((size_t)b * (TT - 1)) * 128;
    int rows = min(64, (TT - 1) - t0);

    if (t0 >= len - 1) {
        for (int idx = threadIdx.x; idx < rows * 64; idx += 256) {
            int m = idx >> 6, n = idx & 63;
            ob[(size_t)(t0 + m) * 128 + n0 + n] = 0.f;
        }
        return;
    }

    __shared__ __align__(16) float sA[64][36];
    __shared__ __align__(16) float sW[64][36];
    ull acc[4][4];
#pragma unroll
    for (int i = 0; i < 4; i++)
#pragma unroll
        for (int j = 0; j < 4; j++) acc[i][j] = 0ull;

    const float* ab = g_out1 + (size_t)(b * TT + t0) * HH;
    int tx = threadIdx.x & 15, ty = threadIdx.x >> 4;

    for (int kc = 0; kc < 128; kc += 32) {
        __syncthreads();
#pragma unroll
        for (int l = 0; l < 8; l++) {
            int idx = threadIdx.x + l * 256;
            int r = idx >> 5, c = idx & 31;
            sA[r][c] = ab[r * HH + kc + c];
            sW[r][c] = Wfc[(size_t)(n0 + r) * CP1 + kc + c];
        }
        __syncthreads();
#pragma unroll
        for (int kq = 0; kq < 8; kq++) {
            ull w[4][2], a[4][2];
#pragma unroll
            for (int j = 0; j < 4; j++) {
                float4 v = *(const float4*)&sW[tx + 16 * j][kq * 4];
                w[j][0] = ((ull*)&v)[0]; w[j][1] = ((ull*)&v)[1];
            }
#pragma unroll
            for (int i = 0; i < 4; i++) {
                float4 v = *(const float4*)&sA[ty + 16 * i][kq * 4];
                a[i][0] = ((ull*)&v)[0]; a[i][1] = ((ull*)&v)[1];
            }
#pragma unroll
            for (int i = 0; i < 4; i++)
#pragma unroll
                for (int j = 0; j < 4; j++) {
                    acc[i][j] = fma2(a[i][0], w[j][0], acc[i][j]);
                    acc[i][j] = fma2(a[i][1], w[j][1], acc[i][j]);
                }
        }
    }
    float at[4], wt[4], bias[4];
#pragma unroll
    for (int i = 0; i < 4; i++) {
        int t = t0 + ty + 16 * i;
        at[i] = x[(size_t)(b * TT + t) * CP1];
    }
#pragma unroll
    for (int j = 0; j < 4; j++) {
        wt[j]   = Wfc[(size_t)(n0 + tx + 16 * j) * CP1 + 128];
        bias[j] = bfc[n0 + tx + 16 * j];
    }
#pragma unroll
    for (int i = 0; i < 4; i++) {
        int t = t0 + ty + 16 * i;
        if (t >= TT - 1) continue;
        float* orow = ob + (size_t)t * 128 + n0;
        bool valid = (t < len - 1);
#pragma unroll
        for (int j = 0; j < 4; j++) {
            float2 p = unpack2(acc[i][j]);
            float v = p.x + p.y + at[i] * wt[j] + bias[j];
            orow[tx + 16 * j] = valid ? v : 0.f;
        }
    }
}

// ---------------- launch -----------------------------------------------------
extern "C" void kernel_launch(void* const* d_in, const int* in_sizes, int n_in,
                              void* d_out, int out_size) {
    const float* x      = (const float*)d_in[0];
    const int*   lens   = (const int*)  d_in[1];
    const float* h0_1   = (const float*)d_in[2];
    const float* h0_2   = (const float*)d_in[3];
    const float* Wih1   = (const float*)d_in[4];
    const float* Whh1   = (const float*)d_in[5];
    const float* bih1   = (const float*)d_in[6];
    const float* bhh1   = (const float*)d_in[7];
    const float* Wih2   = (const float*)d_in[8];
    const float* Whh2   = (const float*)d_in[9];
    const float* bih2   = (const float*)d_in[10];
    const float* bhh2   = (const float*)d_in[11];
    const float* Wfc    = (const float*)d_in[12];
    const float* bfc    = (const float*)d_in[13];
    float* out = (float*)d_out;

    k_gi1  <<<dim3(2, BB, 6), 256>>>(x, lens, Wih1, bih1);
    k_recur1<<<128, 384>>>(lens, h0_1, Whh1, bhh1, h0_2, Wih2, Whh2, bih2, bhh2, out);
    k_fc   <<<dim3(4, BB, 2), 256>>>(x, lens, Wfc, bfc, out);
}

// round 13
// speedup vs baseline: 1.1583x; 1.0252x over previous
#include <cuda_runtime.h>
#include <cuda_bf16.h>
#include <cstdint>

#define BB 256
#define TT 256
#define CP1 129
#define HH 128
#define G1 384
#define PRED_N (BB * (TT - 1) * 128)
#define PAR_N  (BB * TT * 2)

typedef unsigned long long ull;
typedef unsigned int u32;

// ---------------- scratch: __device__ globals -------------------------------
__device__ float g_gi1[(size_t)BB * TT * G1];   // (b,t,384) layer-1 input proj
__device__ float g_out1[(size_t)BB * TT * HH];  // (b,t,128) layer-1 outputs

// ---------------- helpers ----------------------------------------------------
__device__ __forceinline__ ull fma2(ull a, ull b, ull c) {
    ull d; asm("fma.rn.f32x2 %0,%1,%2,%3;" : "=l"(d) : "l"(a), "l"(b), "l"(c));
    return d;
}
__device__ __forceinline__ float2 unpack2(ull v) {
    float lo, hi; asm("mov.b64 {%0,%1},%2;" : "=f"(lo), "=f"(hi) : "l"(v));
    return make_float2(lo, hi);
}
__device__ __forceinline__ float sigf(float v) {
    return __fdividef(1.f, 1.f + __expf(-v));
}
__device__ __forceinline__ float tanh_(float v) {
    return __fdividef(2.f, 1.f + __expf(-2.f * v)) - 1.f;
}
__device__ __forceinline__ u32 f2tf32(float v) {
    u32 r; asm("cvt.rna.tf32.f32 %0, %1;" : "=r"(r) : "f"(v));
    return r;
}

#define MMA_TF32(d, a, b)                                              \
    asm volatile("mma.sync.aligned.m16n8k8.row.col.f32.tf32.tf32.f32 " \
        "{%0,%1,%2,%3}, {%4,%5,%6,%7}, {%8,%9}, {%0,%1,%2,%3};"        \
        : "+f"((d)[0]), "+f"((d)[1]), "+f"((d)[2]), "+f"((d)[3])       \
        : "r"((a)[0]), "r"((a)[1]), "r"((a)[2]), "r"((a)[3]),          \
          "r"((b)[0]), "r"((b)[1]))

// Fragment-packed staging index maps (K-chunk = 32):
// A (128x32): atile = (r>>4)*4 + (c>>3); q = ((r>>3)&1) + 2*((c>>2)&1)
//   dest = atile*128 + ((r&7)*4 + (c&3))*4 + q      -> warp reads LDS.128
// B (64x32):  btile = (r>>3)*4 + (c>>3); q = (c>>2)&1
//   dest = btile*64 + ((r&7)*4 + (c&3))*2 + q       -> warp reads LDS.64
__device__ __forceinline__ int a_dest(int r, int c) {
    return (((r >> 4) * 4 + (c >> 3)) << 7) + (((r & 7) * 4 + (c & 3)) << 2)
         + (((r >> 3) & 1) + (((c >> 2) & 1) << 1));
}
__device__ __forceinline__ int b_dest(int r, int c) {
    return (((r >> 3) * 4 + (c >> 3)) << 6) + (((r & 7) * 4 + (c & 3)) << 1)
         + ((c >> 2) & 1);
}

// ---------------- tf32-3x GEMM body (tile 128m x 64n, K=128) ----------------
// sAh/sAl: 4096 floats each; sBh/sBl: 2048 floats each.
// Result in d[2][4][4]; caller does the k=128 tail + epilogue.
struct GemmSmem {
    __align__(16) float Ah[4096];
    __align__(16) float Al[4096];
    __align__(16) float Bh[2048];
    __align__(16) float Bl[2048];
};

// ---------------- K1: gi1 = x @ Wih1^T + bih1  (tf32-3x, packed frags) ------
__global__ void __launch_bounds__(256) k_gi1(
        const float* __restrict__ x, const int* __restrict__ lengths,
        const float* __restrict__ Wih1, const float* __restrict__ bih1) {
    int t0 = blockIdx.x * 128, b = blockIdx.y, n0 = blockIdx.z * 64;
    if (t0 >= lengths[b]) return;

    __shared__ GemmSmem sm;
    int tid = threadIdx.x;
    int w = tid >> 5, lane = tid & 31;
    int gid = lane >> 2, tig = lane & 3;
    int mb4 = (w & 3) * 8;    // atile base = (mb>>4)*4
    int nb4 = (w >> 2) * 16;  // btile base = (nb>>3)*4

    float d[2][4][4] = {};
    const float* xb = x + (size_t)(b * TT + t0) * CP1;

    for (int kc = 0; kc < 128; kc += 32) {
        __syncthreads();
#pragma unroll
        for (int l = 0; l < 16; l++) {           // A: 128x32
            int idx = tid + l * 256;
            int r = idx >> 5, c = idx & 31;
            float v = xb[r * CP1 + kc + c];
            float hf = __uint_as_float(f2tf32(v));
            int dst = a_dest(r, c);
            sm.Ah[dst] = hf;
            sm.Al[dst] = __uint_as_float(f2tf32(v - hf));
        }
#pragma unroll
        for (int l = 0; l < 8; l++) {            // B: 64x32
            int idx = tid + l * 256;
            int r = idx >> 5, c = idx & 31;
            float v = Wih1[(size_t)(n0 + r) * CP1 + kc + c];
            float hf = __uint_as_float(f2tf32(v));
            int dst = b_dest(r, c);
            sm.Bh[dst] = hf;
            sm.Bl[dst] = __uint_as_float(f2tf32(v - hf));
        }
        __syncthreads();
#pragma unroll
        for (int k8 = 0; k8 < 4; k8++) {
            u32 ah[2][4], al[2][4], bh[4][2], bl[4][2];
#pragma unroll
            for (int mt = 0; mt < 2; mt++) {
                int off = ((mb4 + mt * 4 + k8) << 7) + (lane << 2);
                float4 vh = *(const float4*)&sm.Ah[off];
                float4 vl = *(const float4*)&sm.Al[off];
                ah[mt][0] = __float_as_uint(vh.x); ah[mt][1] = __float_as_uint(vh.y);
                ah[mt][2] = __float_as_uint(vh.z); ah[mt][3] = __float_as_uint(vh.w);
                al[mt][0] = __float_as_uint(vl.x); al[mt][1] = __float_as_uint(vl.y);
                al[mt][2] = __float_as_uint(vl.z); al[mt][3] = __float_as_uint(vl.w);
            }
#pragma unroll
            for (int nt = 0; nt < 4; nt++) {
                int off = ((nb4 + nt * 4 + k8) << 6) + (lane << 1);
                float2 vh = *(const float2*)&sm.Bh[off];
                float2 vl = *(const float2*)&sm.Bl[off];
                bh[nt][0] = __float_as_uint(vh.x); bh[nt][1] = __float_as_uint(vh.y);
                bl[nt][0] = __float_as_uint(vl.x); bl[nt][1] = __float_as_uint(vl.y);
            }
#pragma unroll
            for (int mt = 0; mt < 2; mt++)
#pragma unroll
                for (int nt = 0; nt < 4; nt++) {
                    MMA_TF32(d[mt][nt], al[mt], bh[nt]);
                    MMA_TF32(d[mt][nt], ah[mt], bl[nt]);
                    MMA_TF32(d[mt][nt], ah[mt], bh[nt]);
                }
        }
    }

    // epilogue: k=128 tail + bias + store (fp32)
    int mb = (w & 3) * 32, nb = (w >> 2) * 32;
    float at_[2][2], wt_[4][2], bi_[4][2];
#pragma unroll
    for (int mt = 0; mt < 2; mt++) {
        int r = mb + mt * 16 + gid;
        at_[mt][0] = xb[r * CP1 + 128];
        at_[mt][1] = xb[(r + 8) * CP1 + 128];
    }
#pragma unroll
    for (int nt = 0; nt < 4; nt++) {
        int c0 = n0 + nb + nt * 8 + 2 * tig;
        wt_[nt][0] = Wih1[(size_t)c0 * CP1 + 128];
        wt_[nt][1] = Wih1[(size_t)(c0 + 1) * CP1 + 128];
        bi_[nt][0] = bih1[c0];
        bi_[nt][1] = bih1[c0 + 1];
    }
#pragma unroll
    for (int mt = 0; mt < 2; mt++) {
        int r = mb + mt * 16 + gid;
        float* row0 = g_gi1 + (size_t)(b * TT + t0 + r) * G1 + n0;
        float* row1 = row0 + (size_t)8 * G1;
#pragma unroll
        for (int nt = 0; nt < 4; nt++) {
            int c = nb + nt * 8 + 2 * tig;
            *(float2*)(row0 + c) = make_float2(
                d[mt][nt][0] + at_[mt][0] * wt_[nt][0] + bi_[nt][0],
                d[mt][nt][1] + at_[mt][0] * wt_[nt][1] + bi_[nt][1]);
            *(float2*)(row1 + c) = make_float2(
                d[mt][nt][2] + at_[mt][1] * wt_[nt][0] + bi_[nt][0],
                d[mt][nt][3] + at_[mt][1] * wt_[nt][1] + bi_[nt][1]);
        }
    }
}

// ---------------- K2: fused recurrence (identical to R12) -------------------
__global__ void __launch_bounds__(384, 1)
k_recur1(const int* __restrict__ lengths, const float* __restrict__ h0_1,
         const float* __restrict__ Whh1, const float* __restrict__ bhh1,
         const float* __restrict__ h0_2, const float* __restrict__ Wih2,
         const float* __restrict__ Whh2, const float* __restrict__ bih2,
         const float* __restrict__ bhh2, float* __restrict__ out) {
    int g = threadIdx.x;
    int wid = g >> 5, lane = g & 31;
    ull W2[64];
    const ull* wr = (const ull*)(Whh1 + (size_t)g * HH);
#pragma unroll
    for (int i = 0; i < 64; i++) W2[i] = wr[i];
    float bh = bhh1[g];

    float4 wv2 = make_float4(0.f, 0.f, 0.f, 0.f);
    float bi2 = 0.f;
    if (wid < 6) { wv2 = ((const float4*)Wih2)[wid * 32 + lane]; bi2 = bih2[wid]; }

    __shared__ __align__(16) float s_h[HH];
    __shared__ float s_gh[G1];
    __shared__ float s_gi2[6];
    __shared__ float s_w2[18];
    if (g < 12) s_w2[g] = Whh2[g];
    else if (g < 18) s_w2[g] = bhh2[g - 12];

#pragma unroll 1
    for (int rsel = 0; rsel < 2; rsel++) {
        int b = rsel ? (255 - (int)blockIdx.x) : (int)blockIdx.x;
        int len = lengths[b];
        if (g < HH) s_h[g] = h0_1[b * HH + g];
        float u0 = 0.f, u1 = 0.f;
        if (g == 383) { u0 = h0_2[b * 2]; u1 = h0_2[b * 2 + 1]; }
        __syncthreads();

        const float* gi = g_gi1 + (size_t)b * TT * G1;
        float* o1 = g_out1 + (size_t)b * TT * HH;
        float* par = out + PRED_N + (size_t)b * TT * 2;
        float pr = 0.f, pz = 0.f, pn = 0.f;
        if (g < HH) { pr = gi[g]; pz = gi[HH + g]; pn = gi[2 * HH + g]; }

#pragma unroll 1
        for (int t = 0; t < len; t++) {
            if (wid < 6 && t >= 1) {   // gi2 of out1[t-1] (== current s_h)
                float4 hv = *(const float4*)&s_h[lane * 4];
                float v = hv.x * wv2.x + hv.y * wv2.y + hv.z * wv2.z + hv.w * wv2.w;
                v += __shfl_xor_sync(0xFFFFFFFFu, v, 16);
                v += __shfl_xor_sync(0xFFFFFFFFu, v, 8);
                v += __shfl_xor_sync(0xFFFFFFFFu, v, 4);
                v += __shfl_xor_sync(0xFFFFFFFFu, v, 2);
                v += __shfl_xor_sync(0xFFFFFFFFu, v, 1);
                if (lane == 0) s_gi2[wid] = v + bi2;
            }

            ull a0 = 0ull, a1 = 0ull, a2 = 0ull, a3 = 0ull;
            const ull* h2 = (const ull*)s_h;
#pragma unroll
            for (int i = 0; i < 64; i += 4) {
                a0 = fma2(W2[i],     h2[i],     a0);
                a1 = fma2(W2[i + 1], h2[i + 1], a1);
                a2 = fma2(W2[i + 2], h2[i + 2], a2);
                a3 = fma2(W2[i + 3], h2[i + 3], a3);
            }
            float2 f0 = unpack2(a0), f1 = unpack2(a1);
            float2 f2 = unpack2(a2), f3 = unpack2(a3);
            s_gh[g] = ((f0.x + f0.y) + (f1.x + f1.y)) +
                      ((f2.x + f2.y) + (f3.x + f3.y)) + bh;
            __syncthreads();

            if (g < HH) {
                float r = sigf(pr + s_gh[g]);
                float z = sigf(pz + s_gh[HH + g]);
                float n = tanh_(pn + r * s_gh[2 * HH + g]);
                float hn = (1.f - z) * n + z * s_h[g];
                o1[(size_t)t * HH + g] = hn;
                if (t + 1 < len) {
                    const float* gn = gi + (size_t)(t + 1) * G1;
                    pr = gn[g]; pz = gn[HH + g]; pn = gn[2 * HH + g];
                }
                s_h[g] = hn;
            } else if (g == 383 && t >= 1) {
                float hr0 = s_w2[0]  * u0 + s_w2[1]  * u1 + s_w2[12];
                float hr1 = s_w2[2]  * u0 + s_w2[3]  * u1 + s_w2[13];
                float hz0 = s_w2[4]  * u0 + s_w2[5]  * u1 + s_w2[14];
                float hz1 = s_w2[6]  * u0 + s_w2[7]  * u1 + s_w2[15];
                float hn0 = s_w2[8]  * u0 + s_w2[9]  * u1 + s_w2[16];
                float hn1 = s_w2[10] * u0 + s_w2[11] * u1 + s_w2[17];
                float r0 = sigf(s_gi2[0] + hr0), r1 = sigf(s_gi2[1] + hr1);
                float z0 = sigf(s_gi2[2] + hz0), z1 = sigf(s_gi2[3] + hz1);
                float n0 = tanh_(s_gi2[4] + r0 * hn0), n1 = tanh_(s_gi2[5] + r1 * hn1);
                u0 = (1.f - z0) * n0 + z0 * u0;
                u1 = (1.f - z1) * n1 + z1 * u1;
                par[(t - 1) * 2]     = __expf(-u0);
                par[(t - 1) * 2 + 1] = __expf(-u1);
            }
            __syncthreads();
        }

        if (wid < 6) {
            float4 hv = *(const float4*)&s_h[lane * 4];
            float v = hv.x * wv2.x + hv.y * wv2.y + hv.z * wv2.z + hv.w * wv2.w;
            v += __shfl_xor_sync(0xFFFFFFFFu, v, 16);
            v += __shfl_xor_sync(0xFFFFFFFFu, v, 8);
            v += __shfl_xor_sync(0xFFFFFFFFu, v, 4);
            v += __shfl_xor_sync(0xFFFFFFFFu, v, 2);
            v += __shfl_xor_sync(0xFFFFFFFFu, v, 1);
            if (lane == 0) s_gi2[wid] = v + bi2;
        }
        __syncthreads();
        if (g == 383) {
            float hr0 = s_w2[0]  * u0 + s_w2[1]  * u1 + s_w2[12];
            float hr1 = s_w2[2]  * u0 + s_w2[3]  * u1 + s_w2[13];
            float hz0 = s_w2[4]  * u0 + s_w2[5]  * u1 + s_w2[14];
            float hz1 = s_w2[6]  * u0 + s_w2[7]  * u1 + s_w2[15];
            float hn0 = s_w2[8]  * u0 + s_w2[9]  * u1 + s_w2[16];
            float hn1 = s_w2[10] * u0 + s_w2[11] * u1 + s_w2[17];
            float r0 = sigf(s_gi2[0] + hr0), r1 = sigf(s_gi2[1] + hr1);
            float z0 = sigf(s_gi2[2] + hz0), z1 = sigf(s_gi2[3] + hz1);
            float n0 = tanh_(s_gi2[4] + r0 * hn0), n1 = tanh_(s_gi2[5] + r1 * hn1);
            u0 = (1.f - z0) * n0 + z0 * u0;
            u1 = (1.f - z1) * n1 + z1 * u1;
            par[(len - 1) * 2]     = __expf(-u0);
            par[(len - 1) * 2 + 1] = __expf(-u1);
        }
        for (int tp = len + g; tp < TT; tp += 384) {
            par[tp * 2] = 1.f; par[tp * 2 + 1] = 1.f;
        }
        if (g == 0) out[PRED_N + PAR_N + b] = (float)len;
        __syncthreads();
    }
}

// ---------------- K3: FC head (tf32-3x, packed frags, masked epilogue) ------
__global__ void __launch_bounds__(256) k_fc(
        const float* __restrict__ x, const int* __restrict__ lengths,
        const float* __restrict__ Wfc, const float* __restrict__ bfc,
        float* __restrict__ out) {
    int t0 = blockIdx.x * 128, b = blockIdx.y, n0 = blockIdx.z * 64;
    int len = lengths[b];
    float* ob = out + ((size_t)b * (TT - 1)) * 128;
    int rows = min(128, (TT - 1) - t0);

    if (t0 >= len - 1) {  // fully masked tile: zero-fill, skip GEMM
        for (int idx = threadIdx.x; idx < rows * 64; idx += 256) {
            int m = idx >> 6, n = idx & 63;
            ob[(size_t)(t0 + m) * 128 + n0 + n] = 0.f;
        }
        return;
    }

    __shared__ GemmSmem sm;
    int tid = threadIdx.x;
    int w = tid >> 5, lane = tid & 31;
    int gid = lane >> 2, tig = lane & 3;
    int mb4 = (w & 3) * 8, nb4 = (w >> 2) * 16;

    float d[2][4][4] = {};
    const float* ab = g_out1 + (size_t)(b * TT + t0) * HH;

    for (int kc = 0; kc < 128; kc += 32) {
        __syncthreads();
#pragma unroll
        for (int l = 0; l < 16; l++) {           // A: out1 128x32
            int idx = tid + l * 256;
            int r = idx >> 5, c = idx & 31;
            float v = ab[r * HH + kc + c];
            float hf = __uint_as_float(f2tf32(v));
            int dst = a_dest(r, c);
            sm.Ah[dst] = hf;
            sm.Al[dst] = __uint_as_float(f2tf32(v - hf));
        }
#pragma unroll
        for (int l = 0; l < 8; l++) {            // B: Wfc 64x32
            int idx = tid + l * 256;
            int r = idx >> 5, c = idx & 31;
            float v = Wfc[(size_t)(n0 + r) * CP1 + kc + c];
            float hf = __uint_as_float(f2tf32(v));
            int dst = b_dest(r, c);
            sm.Bh[dst] = hf;
            sm.Bl[dst] = __uint_as_float(f2tf32(v - hf));
        }
        __syncthreads();
#pragma unroll
        for (int k8 = 0; k8 < 4; k8++) {
            u32 ah[2][4], al[2][4], bh[4][2], bl[4][2];
#pragma unroll
            for (int mt = 0; mt < 2; mt++) {
                int off = ((mb4 + mt * 4 + k8) << 7) + (lane << 2);
                float4 vh = *(const float4*)&sm.Ah[off];
                float4 vl = *(const float4*)&sm.Al[off];
                ah[mt][0] = __float_as_uint(vh.x); ah[mt][1] = __float_as_uint(vh.y);
                ah[mt][2] = __float_as_uint(vh.z); ah[mt][3] = __float_as_uint(vh.w);
                al[mt][0] = __float_as_uint(vl.x); al[mt][1] = __float_as_uint(vl.y);
                al[mt][2] = __float_as_uint(vl.z); al[mt][3] = __float_as_uint(vl.w);
            }
#pragma unroll
            for (int nt = 0; nt < 4; nt++) {
                int off = ((nb4 + nt * 4 + k8) << 6) + (lane << 1);
                float2 vh = *(const float2*)&sm.Bh[off];
                float2 vl = *(const float2*)&sm.Bl[off];
                bh[nt][0] = __float_as_uint(vh.x); bh[nt][1] = __float_as_uint(vh.y);
                bl[nt][0] = __float_as_uint(vl.x); bl[nt][1] = __float_as_uint(vl.y);
            }
#pragma unroll
            for (int mt = 0; mt < 2; mt++)
#pragma unroll
                for (int nt = 0; nt < 4; nt++) {
                    MMA_TF32(d[mt][nt], al[mt], bh[nt]);
                    MMA_TF32(d[mt][nt], ah[mt], bl[nt]);
                    MMA_TF32(d[mt][nt], ah[mt], bh[nt]);
                }
        }
    }

    // epilogue: k=128 tail = time feature; mask (t < len-1, t < 255); store
    int mb = (w & 3) * 32, nb = (w >> 2) * 32;
    float at_[2][2], wt_[4][2], bi_[4][2];
#pragma unroll
    for (int mt = 0; mt < 2; mt++) {
        int r = mb + mt * 16 + gid;
        at_[mt][0] = x[(size_t)(b * TT + t0 + r) * CP1];
        at_[mt][1] = x[(size_t)(b * TT + t0 + r + 8) * CP1];
    }
#pragma unroll
    for (int nt = 0; nt < 4; nt++) {
        int c0 = n0 + nb + nt * 8 + 2 * tig;
        wt_[nt][0] = Wfc[(size_t)c0 * CP1 + 128];
        wt_[nt][1] = Wfc[(size_t)(c0 + 1) * CP1 + 128];
        bi_[nt][0] = bfc[c0];
        bi_[nt][1] = bfc[c0 + 1];
    }
#pragma unroll
    for (int mt = 0; mt < 2; mt++) {
#pragma unroll
        for (int half = 0; half < 2; half++) {
            int r = mb + mt * 16 + gid + half * 8;
            int t = t0 + r;
            if (t >= TT - 1) continue;
            bool valid = (t < len - 1);
            float* row = ob + (size_t)t * 128 + n0;
            float av = at_[mt][half];
#pragma unroll
            for (int nt = 0; nt < 4; nt++) {
                int c = nb + nt * 8 + 2 * tig;
                float v0 = d[mt][nt][half * 2]     + av * wt_[nt][0] + bi_[nt][0];
                float v1 = d[mt][nt][half * 2 + 1] + av * wt_[nt][1] + bi_[nt][1];
                *(float2*)(row + c) = valid ? make_float2(v0, v1)
                                            : make_float2(0.f, 0.f);
            }
        }
    }
}

// ---------------- launch -----------------------------------------------------
extern "C" void kernel_launch(void* const* d_in, const int* in_sizes, int n_in,
                              void* d_out, int out_size) {
    const float* x      = (const float*)d_in[0];
    const int*   lens   = (const int*)  d_in[1];
    const float* h0_1   = (const float*)d_in[2];
    const float* h0_2   = (const float*)d_in[3];
    const float* Wih1   = (const float*)d_in[4];
    const float* Whh1   = (const float*)d_in[5];
    const float* bih1   = (const float*)d_in[6];
    const float* bhh1   = (const float*)d_in[7];
    const float* Wih2   = (const float*)d_in[8];
    const float* Whh2   = (const float*)d_in[9];
    const float* bih2   = (const float*)d_in[10];
    const float* bhh2   = (const float*)d_in[11];
    const float* Wfc    = (const float*)d_in[12];
    const float* bfc    = (const float*)d_in[13];
    float* out = (float*)d_out;

    k_gi1  <<<dim3(2, BB, 6), 256>>>(x, lens, Wih1, bih1);
    k_recur1<<<128, 384>>>(lens, h0_1, Whh1, bhh1, h0_2, Wih2, Whh2, bih2, bhh2, out);
    k_fc   <<<dim3(2, BB, 2), 256>>>(x, lens, Wfc, bfc, out);
}